// round 13
// baseline (speedup 1.0000x reference)
#include <cuda_runtime.h>
#include <math.h>

#define BATCH 8192
#define DIM   2048
#define FROWS 32                 // rows per block
#define FGRID (BATCH / FROWS)    // 256 blocks
#define FTH   256                // 8 warps: warp = segment, lane = row

// ---------------- device scratch (no allocations allowed) ----------------
__device__ unsigned long long g_acc;    // fixed-point (2^32) sum of logp (zero-init)
__device__ unsigned           g_done;   // block completion counter (zero-init)

// ---------------- 3x3 helpers ----------------
#define MATMUL(r0, r1, r2)                                                   \
    do {                                                                     \
        float n00 = fmaf(m00, (r0).x, fmaf(m01, (r1).x, m02 * (r2).x));      \
        float n01 = fmaf(m00, (r0).y, fmaf(m01, (r1).y, m02 * (r2).y));      \
        float n02 = fmaf(m00, (r0).z, fmaf(m01, (r1).z, m02 * (r2).z));      \
        float n10 = fmaf(m10, (r0).x, fmaf(m11, (r1).x, m12 * (r2).x));      \
        float n11 = fmaf(m10, (r0).y, fmaf(m11, (r1).y, m12 * (r2).y));      \
        float n12 = fmaf(m10, (r0).z, fmaf(m11, (r1).z, m12 * (r2).z));      \
        float n20 = fmaf(m20, (r0).x, fmaf(m21, (r1).x, m22 * (r2).x));      \
        float n21 = fmaf(m20, (r0).y, fmaf(m21, (r1).y, m22 * (r2).y));      \
        float n22 = fmaf(m20, (r0).z, fmaf(m21, (r1).z, m22 * (r2).z));      \
        m00 = n00; m01 = n01; m02 = n02;                                     \
        m10 = n10; m11 = n11; m12 = n12;                                     \
        m20 = n20; m21 = n21; m22 = n22;                                     \
    } while (0)

// apply pending power-of-2 scale (exact identity on tracked value), measure new one
#define MAM()                                                       \
    do {                                                            \
        m00 *= scp; m01 *= scp; m02 *= scp;                         \
        m10 *= scp; m11 *= scp; m12 *= scp;                         \
        m20 *= scp; m21 *= scp; m22 *= scp;                         \
        etot += ep;                                                 \
        float s_ = m00 + m01 + m02;                                 \
        unsigned eb_ = __float_as_uint(s_) >> 23;                   \
        ep  = (int)eb_ - 127;                                       \
        scp = __uint_as_float((254u - eb_) << 23);                  \
    } while (0)

#define MULVEC(r0, r1, r2)                                          \
    do {                                                            \
        float n0 = fmaf(v0, (r0).x, fmaf(v1, (r1).x, v2 * (r2).x)); \
        float n1 = fmaf(v0, (r0).y, fmaf(v1, (r1).y, v2 * (r2).y)); \
        float n2 = fmaf(v0, (r0).z, fmaf(v1, (r1).z, v2 * (r2).z)); \
        v0 = n0; v1 = n1; v2 = n2;                                  \
    } while (0)

#define VAM()                                                       \
    do {                                                            \
        v0 *= scp; v1 *= scp; v2 *= scp; etot += ep;                \
        float s_ = v0 + v1 + v2;                                    \
        unsigned eb_ = __float_as_uint(s_) >> 23;                   \
        ep  = (int)eb_ - 127;                                       \
        scp = __uint_as_float((254u - eb_) << 23);                  \
    } while (0)

// =========================== fully fused kernel ===========================
__global__ void __launch_bounds__(FTH) hmm_kernel(const int*   __restrict__ y,
                                                  const float* __restrict__ T,
                                                  const float* __restrict__ E,
                                                  const float* __restrict__ S,
                                                  float*       __restrict__ out) {
    __shared__ float4   t1[768];            // 256 x (8-step K product), 12 KB
    __shared__ float4   t7[384];            // 128 x (7-step K prefix),   6 KB
    __shared__ unsigned sw[FROWS][65];      // packed bits, stride 65 -> no conflicts
    __shared__ float    cmb[FROWS][71];     // 7 segs x (9 mat + etot), stride 71
    __shared__ float    s_pi[4];
    __shared__ float    s_e[2][4];

    int tid  = threadIdx.x;
    int lane = tid & 31;
    int wid  = tid >> 5;

    // ---------- Phase 1: ballot-pack this block's 32 rows of y ----------
    // warp handles 8 tasks of 1024 consecutive ints; lane r gets ballot r.
    #pragma unroll 1
    for (int k = 0; k < 8; k++) {
        int task = wid * 8 + k;                      // 0..63
        int row  = task >> 1;
        const int* p = y + ((size_t)(blockIdx.x * FROWS + row)) * DIM
                         + (task & 1) * 1024;
        unsigned my = 0;
        #pragma unroll
        for (int r = 0; r < 32; r++) {
            int v = __ldcs(p + r * 32 + lane);       // streaming, coalesced 128B
            unsigned b = __ballot_sync(0xFFFFFFFFu, v != 0);
            if (lane == r) my = b;
        }
        sw[row][(task & 1) * 32 + lane] = my;
    }

    // ---------- Phase 2: fp32 table compute (overlaps other blocks' DRAM) ----
    {
        float W[3][3], e[2][3];
        #pragma unroll
        for (int i = 0; i < 3; i++) {
            float a0 = T[i * 3 + 0], a1 = T[i * 3 + 1], a2 = T[i * 3 + 2];
            float m = fmaxf(a0, fmaxf(a1, a2));
            float x0 = expf(a0 - m), x1 = expf(a1 - m), x2 = expf(a2 - m);
            float Z = x0 + x1 + x2;
            W[i][0] = x0 / Z; W[i][1] = x1 / Z; W[i][2] = x2 / Z;
            float u = E[i * 2 + 0], w = E[i * 2 + 1];
            float mm = fmaxf(u, w);
            float eu = expf(u - mm), ew = expf(w - mm);
            float Ze = eu + ew;
            e[0][i] = eu / Ze;                       // P(obs=0 | state i)
            e[1][i] = ew / Ze;                       // P(obs=1 | state i)
        }
        int byte = tid;                              // 0..255, one tab1 entry each
        float P[3][3];
        {
            int b0 = byte & 1;
            #pragma unroll
            for (int i = 0; i < 3; i++)
                #pragma unroll
                for (int j = 0; j < 3; j++) P[i][j] = e[b0][i] * W[i][j];
        }
        #pragma unroll
        for (int t = 1; t < 7; t++) {                // steps 1..6 -> 7-step prefix
            int bt = (byte >> t) & 1;
            float Q[3][3];
            #pragma unroll
            for (int i = 0; i < 3; i++)
                #pragma unroll
                for (int j = 0; j < 3; j++)
                    Q[i][j] = P[i][0] * (e[bt][0] * W[0][j])
                            + P[i][1] * (e[bt][1] * W[1][j])
                            + P[i][2] * (e[bt][2] * W[2][j]);
            #pragma unroll
            for (int i = 0; i < 3; i++)
                #pragma unroll
                for (int j = 0; j < 3; j++) P[i][j] = Q[i][j];
        }
        if (byte < 128) {                            // save 7-step prefix
            #pragma unroll
            for (int i = 0; i < 3; i++)
                t7[byte * 3 + i] = make_float4(P[i][0], P[i][1], P[i][2], 0.f);
        }
        {                                            // 8th step -> tab1
            int b7 = (byte >> 7) & 1;
            float Q[3][3];
            #pragma unroll
            for (int i = 0; i < 3; i++)
                #pragma unroll
                for (int j = 0; j < 3; j++)
                    Q[i][j] = P[i][0] * (e[b7][0] * W[0][j])
                            + P[i][1] * (e[b7][1] * W[1][j])
                            + P[i][2] * (e[b7][2] * W[2][j]);
            #pragma unroll
            for (int i = 0; i < 3; i++)
                t1[byte * 3 + i] = make_float4(Q[i][0], Q[i][1], Q[i][2], 0.f);
        }
        if (tid == 0) {
            float s0 = S[0], s1 = S[1], s2 = S[2];
            float m = fmaxf(s0, fmaxf(s1, s2));
            float a = expf(s0 - m), b = expf(s1 - m), d = expf(s2 - m);
            float Z = a + b + d;
            s_pi[0] = a / Z; s_pi[1] = b / Z; s_pi[2] = d / Z; s_pi[3] = 0.f;
            #pragma unroll
            for (int j = 0; j < 3; j++) { s_e[0][j] = e[0][j]; s_e[1][j] = e[1][j]; }
        }
    }
    __syncthreads();

    // ---------- Phase 3: segmented forward chain (warp = segment, lane = row) --
    int row = lane, seg = wid;
    unsigned wds[8];
    #pragma unroll
    for (int k = 0; k < 8; k++) wds[k] = sw[row][seg * 8 + k];   // conflict-free

    int   etot = 0, ep = 0;
    float scp = 1.0f;

    if (seg == 0) {
        float v0 = s_pi[0], v1 = s_pi[1], v2 = s_pi[2];
        #pragma unroll 4
        for (int k = 0; k < 8; k++) {
            unsigned w = wds[k];
            unsigned b0 = w & 255u, b1 = (w >> 8) & 255u;
            unsigned b2 = (w >> 16) & 255u, b3 = w >> 24;
            MULVEC(t1[b0 * 3], t1[b0 * 3 + 1], t1[b0 * 3 + 2]);
            MULVEC(t1[b1 * 3], t1[b1 * 3 + 1], t1[b1 * 3 + 2]);
            VAM();
            MULVEC(t1[b2 * 3], t1[b2 * 3 + 1], t1[b2 * 3 + 2]);
            MULVEC(t1[b3 * 3], t1[b3 * 3 + 1], t1[b3 * 3 + 2]);
            VAM();
        }
        __syncthreads();                              // wait for matrix segs

        // combine: v <- v * M1 * ... * M7 with exponent tracking
        #pragma unroll 1
        for (int s = 0; s < 7; s++) {
            const float* M = &cmb[row][s * 10];
            float n0 = fmaf(v0, M[0], fmaf(v1, M[3], v2 * M[6]));
            float n1 = fmaf(v0, M[1], fmaf(v1, M[4], v2 * M[7]));
            float n2 = fmaf(v0, M[2], fmaf(v1, M[5], v2 * M[8]));
            etot += __float_as_int(M[9]);
            float s_ = n0 + n1 + n2;
            unsigned eb = __float_as_uint(s_) >> 23;
            etot += (int)eb - 127;
            float sc = __uint_as_float((254u - eb) << 23);
            v0 = n0 * sc; v1 = n1 * sc; v2 = n2 * sc;
        }
        float logp = logf(v0 + v1 + v2) + (float)etot * 0.69314718055994530942f;

        // warp reduce over the 32 rows, then deterministic fixed-point atomic
        double d = (double)logp;
        #pragma unroll
        for (int off = 16; off > 0; off >>= 1)
            d += __shfl_down_sync(0xFFFFFFFFu, d, off);

        if (lane == 0) {
            long long fx = __double2ll_rn(d * 4294967296.0);     // 2^32 fixed point
            atomicAdd(&g_acc, (unsigned long long)fx);           // exact, associative
            __threadfence();
            unsigned prev = atomicAdd(&g_done, 1u);
            if (prev == FGRID - 1) {
                unsigned long long a = atomicAdd(&g_acc, 0ull);  // ordered read
                double tot = (double)(long long)a * (1.0 / 4294967296.0);
                out[0] = (float)(tot / (double)BATCH);
                __threadfence();
                atomicExch(&g_acc, 0ull);                        // reset for replay
                atomicExch(&g_done, 0u);
            }
        }
    } else {
        float m00 = 1.f, m01 = 0.f, m02 = 0.f;
        float m10 = 0.f, m11 = 1.f, m12 = 0.f;
        float m20 = 0.f, m21 = 0.f, m22 = 1.f;
        #pragma unroll 2
        for (int k = 0; k < 7; k++) {
            unsigned w = wds[k];
            unsigned b0 = w & 255u, b1 = (w >> 8) & 255u;
            unsigned b2 = (w >> 16) & 255u, b3 = w >> 24;
            MATMUL(t1[b0 * 3], t1[b0 * 3 + 1], t1[b0 * 3 + 2]);
            MATMUL(t1[b1 * 3], t1[b1 * 3 + 1], t1[b1 * 3 + 2]);
            MAM();
            MATMUL(t1[b2 * 3], t1[b2 * 3 + 1], t1[b2 * 3 + 2]);
            MATMUL(t1[b3 * 3], t1[b3 * 3 + 1], t1[b3 * 3 + 2]);
            MAM();
        }
        {   // last word of this segment
            unsigned w = wds[7];
            unsigned b0 = w & 255u, b1 = (w >> 8) & 255u;
            unsigned b2 = (w >> 16) & 255u, b3 = w >> 24;
            MATMUL(t1[b0 * 3], t1[b0 * 3 + 1], t1[b0 * 3 + 2]);
            MATMUL(t1[b1 * 3], t1[b1 * 3 + 1], t1[b1 * 3 + 2]);
            MAM();
            MATMUL(t1[b2 * 3], t1[b2 * 3 + 1], t1[b2 * 3 + 2]);
            if (seg == 7) {
                // final byte of the row: 7-step prefix, columns scaled by e[b7]
                unsigned idx = b3 & 127u, sel = b3 >> 7;
                MATMUL(t7[idx * 3], t7[idx * 3 + 1], t7[idx * 3 + 2]);
                float c0 = s_e[sel][0], c1 = s_e[sel][1], c2 = s_e[sel][2];
                m00 *= c0; m01 *= c1; m02 *= c2;
                m10 *= c0; m11 *= c1; m12 *= c2;
                m20 *= c0; m21 *= c1; m22 *= c2;
            } else {
                MATMUL(t1[b3 * 3], t1[b3 * 3 + 1], t1[b3 * 3 + 2]);
            }
            MAM();
        }
        float* c = &cmb[row][(seg - 1) * 10];
        c[0] = m00; c[1] = m01; c[2] = m02;
        c[3] = m10; c[4] = m11; c[5] = m12;
        c[6] = m20; c[7] = m21; c[8] = m22;
        c[9] = __int_as_float(etot);                 // pending (scp,ep) is identity
        __syncthreads();                             // release seg0 combine
    }
}

// ---------------- launch: ONE graph node ----------------
extern "C" void kernel_launch(void* const* d_in, const int* in_sizes, int n_in,
                              void* d_out, int out_size) {
    const int*   y = (const int*)d_in[0];
    const float* T = (const float*)d_in[1];
    const float* E = (const float*)d_in[2];
    const float* S = (const float*)d_in[3];

    hmm_kernel<<<FGRID, FTH>>>(y, T, E, S, (float*)d_out);
}